// round 6
// baseline (speedup 1.0000x reference)
#include <cuda_runtime.h>

#define N_NODES  50000
#define N_EDGES  800000
#define CH       128
#define N_GRAPHS 512
#define OUT_CH   8

// ---------------- scratch (device globals; no allocation allowed) ----------------
__device__ __align__(16) float g_h[N_NODES * CH];       // activations between layers
__device__ __align__(16) float g_yrel[N_NODES * CH];    // h @ Wrel
__device__ __align__(16) float g_yroot[N_NODES * CH];   // h @ Wroot
__device__ __align__(16) float g_agg[N_NODES * CH];     // scatter accumulator
__device__ __align__(16) float g_deg[N_NODES];
__device__ __align__(16) float g_pooled[N_GRAPHS * CH];
__device__ __align__(16) float g_cnt[N_GRAPHS];

// ---------------- zero init -------------------------------------------------------
__global__ void zero_kernel() {
    int idx = blockIdx.x * blockDim.x + threadIdx.x;   // grid covers 1.6M
    float4 z = make_float4(0.f, 0.f, 0.f, 0.f);
    if (idx < N_NODES * CH / 4)  ((float4*)g_agg)[idx]    = z;
    if (idx < N_NODES / 4)       ((float4*)g_deg)[idx]    = z;
    if (idx < N_GRAPHS * CH / 4) ((float4*)g_pooled)[idx] = z;
    if (idx < N_GRAPHS / 4)      ((float4*)g_cnt)[idx]    = z;
}
// tail of g_deg (50000 not divisible by 4 -> 50000/4=12500 exactly; it is. keep anyway)

// ---------------- degree (once per call) ------------------------------------------
// edge_index is int32 (JAX x64 disabled downcasts int64 -> int32)
__global__ void deg_kernel(const int* __restrict__ ei) {
    int e = blockIdx.x * blockDim.x + threadIdx.x;
    if (e < N_EDGES) atomicAdd(&g_deg[ei[N_EDGES + e]], 1.0f);
}

// ---------------- dual GEMM: yrel = A@Wrel, yroot = A@Wroot ----------------------
// BM=128, BN=128(full), BK=16, 256 threads, 8x8 per-thread tile.
#define BM 128
#define BK 16
__global__ __launch_bounds__(256, 2)
void gemm_dual(const float* __restrict__ X, int use_x,
               const float* __restrict__ Wrel, const float* __restrict__ Wroot) {
    const float* A = use_x ? X : g_h;
    const float* W = (blockIdx.y == 0) ? Wrel : Wroot;
    float*       C = (blockIdx.y == 0) ? g_yrel : g_yroot;

    __shared__ float As[BK][BM];   // transposed A tile
    __shared__ float Bs[BK][CH];

    int tid = threadIdx.x;
    int ty  = tid >> 4;            // 0..15
    int tx  = tid & 15;            // 0..15
    int mBase = blockIdx.x * BM;

    float acc[8][8];
    #pragma unroll
    for (int i = 0; i < 8; i++)
        #pragma unroll
        for (int j = 0; j < 8; j++) acc[i][j] = 0.f;

    for (int k0 = 0; k0 < CH; k0 += BK) {
        // A tile: 128x16 = 512 float4 slots, 2 per thread (store transposed)
        #pragma unroll
        for (int t = 0; t < 2; t++) {
            int s   = tid + t * 256;
            int row = s >> 2;
            int c4  = s & 3;
            int m   = mBase + row;
            float4 v = make_float4(0.f, 0.f, 0.f, 0.f);
            if (m < N_NODES) v = *(const float4*)(A + (size_t)m * CH + k0 + c4 * 4);
            As[c4 * 4 + 0][row] = v.x;
            As[c4 * 4 + 1][row] = v.y;
            As[c4 * 4 + 2][row] = v.z;
            As[c4 * 4 + 3][row] = v.w;
        }
        // W tile: 16x128 natural layout
        #pragma unroll
        for (int t = 0; t < 2; t++) {
            int s   = tid + t * 256;
            int row = s >> 5;
            int c4  = s & 31;
            *(float4*)(&Bs[row][c4 * 4]) =
                *(const float4*)(W + (size_t)(k0 + row) * CH + c4 * 4);
        }
        __syncthreads();

        #pragma unroll
        for (int k = 0; k < BK; k++) {
            float ra[8], rb[8];
            #pragma unroll
            for (int i = 0; i < 8; i++) ra[i] = As[k][ty * 8 + i];
            #pragma unroll
            for (int j = 0; j < 8; j++) rb[j] = Bs[k][tx * 8 + j];
            #pragma unroll
            for (int i = 0; i < 8; i++)
                #pragma unroll
                for (int j = 0; j < 8; j++) acc[i][j] += ra[i] * rb[j];
        }
        __syncthreads();
    }

    #pragma unroll
    for (int i = 0; i < 8; i++) {
        int m = mBase + ty * 8 + i;
        if (m < N_NODES) {
            float4 v0 = make_float4(acc[i][0], acc[i][1], acc[i][2], acc[i][3]);
            float4 v1 = make_float4(acc[i][4], acc[i][5], acc[i][6], acc[i][7]);
            *(float4*)(C + (size_t)m * CH + tx * 8)     = v0;
            *(float4*)(C + (size_t)m * CH + tx * 8 + 4) = v1;
        }
    }
}

// ---------------- scatter: warp per edge, float4 vector reductions ---------------
__global__ void scatter_kernel(const int* __restrict__ ei) {
    int gid  = blockIdx.x * blockDim.x + threadIdx.x;
    int e    = gid >> 5;
    if (e >= N_EDGES) return;
    int lane = gid & 31;
    int s = ei[e];
    int d = ei[N_EDGES + e];
    float4 v = ((const float4*)(g_yrel + (size_t)s * CH))[lane];
    float* p = g_agg + (size_t)d * CH + lane * 4;
    asm volatile("red.global.add.v4.f32 [%0], {%1, %2, %3, %4};"
                 :: "l"(p), "f"(v.x), "f"(v.y), "f"(v.z), "f"(v.w) : "memory");
}

// ---------------- combine: h = act(agg/deg + yroot + brel); re-zero agg ----------
__global__ void combine_kernel(const float* __restrict__ brel, int do_relu) {
    int idx = blockIdx.x * blockDim.x + threadIdx.x;   // over N_NODES*32 float4s
    if (idx >= N_NODES * CH / 4) return;
    int i  = idx >> 5;
    int c4 = idx & 31;
    float4 a = ((float4*)g_agg)[idx];
    ((float4*)g_agg)[idx] = make_float4(0.f, 0.f, 0.f, 0.f);   // keep invariant
    float4 r  = ((const float4*)g_yroot)[idx];
    float4 b  = ((const float4*)brel)[c4];
    float inv = 1.0f / fmaxf(g_deg[i], 1.0f);
    float4 o;
    o.x = a.x * inv + r.x + b.x;
    o.y = a.y * inv + r.y + b.y;
    o.z = a.z * inv + r.z + b.z;
    o.w = a.w * inv + r.w + b.w;
    if (do_relu) {
        o.x = fmaxf(o.x, 0.f); o.y = fmaxf(o.y, 0.f);
        o.z = fmaxf(o.z, 0.f); o.w = fmaxf(o.w, 0.f);
    }
    ((float4*)g_h)[idx] = o;
}

// ---------------- global mean pool ------------------------------------------------
__global__ void pool_kernel(const int* __restrict__ batch) {
    int gid = blockIdx.x * blockDim.x + threadIdx.x;
    int i   = gid >> 5;
    if (i >= N_NODES) return;
    int lane = gid & 31;
    int b = batch[i];
    float4 v = ((const float4*)(g_h + (size_t)i * CH))[lane];
    float* p = g_pooled + (size_t)b * CH + lane * 4;
    asm volatile("red.global.add.v4.f32 [%0], {%1, %2, %3, %4};"
                 :: "l"(p), "f"(v.x), "f"(v.y), "f"(v.z), "f"(v.w) : "memory");
    if (lane == 0) atomicAdd(&g_cnt[b], 1.0f);
}

// ---------------- MLP head: one block per graph -----------------------------------
__global__ void mlp_kernel(const float* __restrict__ W1, const float* __restrict__ b1,
                           const float* __restrict__ W2, const float* __restrict__ b2,
                           const float* __restrict__ Wo, const float* __restrict__ bo,
                           float* __restrict__ out) {
    __shared__ float s0[CH], s1[CH];
    int b = blockIdx.x, t = threadIdx.x;
    float c = fmaxf(g_cnt[b], 1.0f);
    s0[t] = g_pooled[b * CH + t] / c;
    __syncthreads();
    float acc = b1[t];
    #pragma unroll 8
    for (int k = 0; k < CH; k++) acc += s0[k] * W1[k * CH + t];
    s1[t] = fmaxf(acc, 0.f);
    __syncthreads();
    acc = b2[t];
    #pragma unroll 8
    for (int k = 0; k < CH; k++) acc += s1[k] * W2[k * CH + t];
    __syncthreads();           // make sure all s0 reads are done before overwrite
    s0[t] = fmaxf(acc, 0.f);
    __syncthreads();
    if (t < OUT_CH) {
        float a = bo[t];
        #pragma unroll 8
        for (int k = 0; k < CH; k++) a += s0[k] * Wo[k * OUT_CH + t];
        out[b * OUT_CH + t] = a;
    }
}

// ---------------- launch ----------------------------------------------------------
extern "C" void kernel_launch(void* const* d_in, const int* in_sizes, int n_in,
                              void* d_out, int out_size) {
    const float* x     = (const float*)d_in[0];
    const int*   ei    = (const int*)d_in[1];    // int32! (JAX default x64-disabled)
    const int*   batch = (const int*)d_in[2];
    const float* Wrel1 = (const float*)d_in[3];
    const float* brel1 = (const float*)d_in[4];
    const float* Wroot1= (const float*)d_in[5];
    const float* Wrel2 = (const float*)d_in[6];
    const float* brel2 = (const float*)d_in[7];
    const float* Wroot2= (const float*)d_in[8];
    const float* Wrel3 = (const float*)d_in[9];
    const float* brel3 = (const float*)d_in[10];
    const float* Wroot3= (const float*)d_in[11];
    const float* W1 = (const float*)d_in[12];
    const float* b1 = (const float*)d_in[13];
    const float* W2 = (const float*)d_in[14];
    const float* b2 = (const float*)d_in[15];
    const float* Wo = (const float*)d_in[16];
    const float* bo = (const float*)d_in[17];
    float* out = (float*)d_out;

    zero_kernel<<<6250, 256>>>();
    deg_kernel<<<(N_EDGES + 255) / 256, 256>>>(ei);

    dim3 ggrid((N_NODES + BM - 1) / BM, 2);
    const int scatter_blocks = N_EDGES * 32 / 256;              // 100000
    const int comb_blocks    = (N_NODES * CH / 4 + 255) / 256;  // 6250

    // layer 1 (input = x)
    gemm_dual<<<ggrid, 256>>>(x, 1, Wrel1, Wroot1);
    scatter_kernel<<<scatter_blocks, 256>>>(ei);
    combine_kernel<<<comb_blocks, 256>>>(brel1, 1);
    // layer 2
    gemm_dual<<<ggrid, 256>>>(x, 0, Wrel2, Wroot2);
    scatter_kernel<<<scatter_blocks, 256>>>(ei);
    combine_kernel<<<comb_blocks, 256>>>(brel2, 1);
    // layer 3 (no relu)
    gemm_dual<<<ggrid, 256>>>(x, 0, Wrel3, Wroot3);
    scatter_kernel<<<scatter_blocks, 256>>>(ei);
    combine_kernel<<<comb_blocks, 256>>>(brel3, 0);

    // pool + head
    pool_kernel<<<(N_NODES * 32 + 255) / 256, 256>>>(batch);
    mlp_kernel<<<N_GRAPHS, CH>>>(W1, b1, W2, b2, Wo, bo, out);
}